// round 1
// baseline (speedup 1.0000x reference)
#include <cuda_runtime.h>
#include <math.h>

// Problem constants (match reference_code)
#define BB    8
#define CIN   3
#define COUT  16
#define HH    384
#define WW    384
#define HWSZ  (HH * WW)           // 147456
#define NPIX  (BB * HWSZ)         // 1179648  (divisible by 256)
#define NELEM (BB * COUT * HWSZ)  // 18874368
#define MAX_ITERS 12
#define THREADS 256
#define NBLOCKS (NPIX / THREADS)  // 4608

// Device-global state (no allocations allowed). Reset every launch by init_kernel
// because CUDA-graph replays reuse the same globals.
__device__ float g_sums[MAX_ITERS + 1];
__device__ int   g_done;

__global__ void init_kernel() {
    int i = threadIdx.x;
    if (i <= MAX_ITERS) g_sums[i] = 0.0f;
    if (i == 0) g_done = 0;
}

// Block-wide sum of 'val' then one atomicAdd into *target.
__device__ __forceinline__ void block_reduce_add(float val, float* target) {
    #pragma unroll
    for (int off = 16; off; off >>= 1)
        val += __shfl_down_sync(0xffffffffu, val, off);
    __shared__ float warpsum[THREADS / 32];
    int lane = threadIdx.x & 31;
    int wid  = threadIdx.x >> 5;
    if (lane == 0) warpsum[wid] = val;
    __syncthreads();
    if (wid == 0) {
        val = (lane < THREADS / 32) ? warpsum[lane] : 0.0f;
        #pragma unroll
        for (int off = 16; off; off >>= 1)
            val += __shfl_down_sync(0xffffffffu, val, off);
        if (lane == 0) atomicAdd(target, val);
    }
}

// Stage 1: v = w_pre @ x + b_pre   (3 -> 16 channels), accumulate sum|v| into g_sums[0].
__global__ void __launch_bounds__(THREADS)
pre_kernel(const float* __restrict__ x,
           const float* __restrict__ w_pre,
           const float* __restrict__ b_pre,
           float* __restrict__ v) {
    __shared__ float sw[COUT * CIN];
    __shared__ float sb[COUT];
    if (threadIdx.x < COUT * CIN) sw[threadIdx.x] = w_pre[threadIdx.x];
    if (threadIdx.x < COUT)       sb[threadIdx.x] = b_pre[threadIdx.x];
    __syncthreads();

    int p  = blockIdx.x * THREADS + threadIdx.x;   // p < NPIX always (exact grid)
    int b  = p / HWSZ;
    int hw = p - b * HWSZ;

    float xin[CIN];
    #pragma unroll
    for (int c = 0; c < CIN; c++)
        xin[c] = x[(b * CIN + c) * HWSZ + hw];

    float local = 0.0f;
    #pragma unroll
    for (int o = 0; o < COUT; o++) {
        float acc = sb[o];
        #pragma unroll
        for (int c = 0; c < CIN; c++)
            acc = fmaf(sw[o * CIN + c], xin[c], acc);
        v[(b * COUT + o) * HWSZ + hw] = acc;
        local += fabsf(acc);
    }
    block_reduce_add(local, &g_sums[0]);
}

// Loop body: if mean(|v|) from previous stage >= 3 (or already done) -> no-op.
// Else: v = 10 * (w_loop @ tanh(w_shared @ v + b_shared) + b_loop), in place,
// accumulating sum|v_new| into g_sums[iter+1].
__global__ void __launch_bounds__(THREADS)
body_kernel(const float* __restrict__ w_shared,
            const float* __restrict__ b_shared,
            const float* __restrict__ w_loop,
            const float* __restrict__ b_loop,
            float* __restrict__ v,
            int iter) {
    // Uniform decision across the whole launch: g_sums[iter] was finalized by the
    // previous launch (stream/graph ordering).
    const float mean = g_sums[iter] * (1.0f / (float)NELEM);
    if (g_done || !(mean < 3.0f)) {
        if (threadIdx.x == 0) g_done = 1;   // benign multi-writer of identical value
        return;
    }

    __shared__ float ws[COUT * COUT];
    __shared__ float wl[COUT * COUT];
    __shared__ float bs[COUT];
    __shared__ float bl[COUT];
    if (threadIdx.x < COUT * COUT) {
        ws[threadIdx.x] = w_shared[threadIdx.x];
        wl[threadIdx.x] = w_loop[threadIdx.x];
    }
    if (threadIdx.x < COUT) {
        bs[threadIdx.x] = b_shared[threadIdx.x];
        bl[threadIdx.x] = b_loop[threadIdx.x];
    }
    __syncthreads();

    int p  = blockIdx.x * THREADS + threadIdx.x;
    int b  = p / HWSZ;
    int hw = p - b * HWSZ;
    const int base = b * COUT * HWSZ + hw;

    float vin[COUT];
    #pragma unroll
    for (int c = 0; c < COUT; c++)
        vin[c] = v[base + c * HWSZ];

    float t[COUT];
    #pragma unroll
    for (int o = 0; o < COUT; o++) {
        float acc = bs[o];
        #pragma unroll
        for (int c = 0; c < COUT; c++)
            acc = fmaf(ws[o * COUT + c], vin[c], acc);
        t[o] = tanhf(acc);
    }

    float local = 0.0f;
    #pragma unroll
    for (int o = 0; o < COUT; o++) {
        float acc = bl[o];
        #pragma unroll
        for (int c = 0; c < COUT; c++)
            acc = fmaf(wl[o * COUT + c], t[c], acc);
        acc *= 10.0f;
        v[base + o * HWSZ] = acc;
        local += fabsf(acc);
    }
    block_reduce_add(local, &g_sums[iter + 1]);
}

// Final stage: out = w_shared @ v + b_shared, in place on d_out.
__global__ void __launch_bounds__(THREADS)
final_kernel(const float* __restrict__ w_shared,
             const float* __restrict__ b_shared,
             float* __restrict__ v) {
    __shared__ float ws[COUT * COUT];
    __shared__ float bs[COUT];
    if (threadIdx.x < COUT * COUT) ws[threadIdx.x] = w_shared[threadIdx.x];
    if (threadIdx.x < COUT)        bs[threadIdx.x] = b_shared[threadIdx.x];
    __syncthreads();

    int p  = blockIdx.x * THREADS + threadIdx.x;
    int b  = p / HWSZ;
    int hw = p - b * HWSZ;
    const int base = b * COUT * HWSZ + hw;

    float vin[COUT];
    #pragma unroll
    for (int c = 0; c < COUT; c++)
        vin[c] = v[base + c * HWSZ];

    #pragma unroll
    for (int o = 0; o < COUT; o++) {
        float acc = bs[o];
        #pragma unroll
        for (int c = 0; c < COUT; c++)
            acc = fmaf(ws[o * COUT + c], vin[c], acc);
        v[base + o * HWSZ] = acc;
    }
}

extern "C" void kernel_launch(void* const* d_in, const int* in_sizes, int n_in,
                              void* d_out, int out_size) {
    const float* x        = (const float*)d_in[0];
    const float* w_pre    = (const float*)d_in[1];
    const float* b_pre    = (const float*)d_in[2];
    const float* w_loop   = (const float*)d_in[3];
    const float* b_loop   = (const float*)d_in[4];
    const float* w_shared = (const float*)d_in[5];
    const float* b_shared = (const float*)d_in[6];
    float* out = (float*)d_out;   // also serves as the in-place v buffer

    init_kernel<<<1, 64>>>();
    pre_kernel<<<NBLOCKS, THREADS>>>(x, w_pre, b_pre, out);
    for (int i = 0; i < MAX_ITERS; i++)
        body_kernel<<<NBLOCKS, THREADS>>>(w_shared, b_shared, w_loop, b_loop, out, i);
    final_kernel<<<NBLOCKS, THREADS>>>(w_shared, b_shared, out);
}

// round 2
// speedup vs baseline: 1.5818x; 1.5818x over previous
#include <cuda_runtime.h>
#include <math.h>

// ---------------- problem constants ----------------
#define BB    8
#define CIN   3
#define COUT  16
#define HWSZ  147456                 // 384*384
#define NPIX  (BB * HWSZ)            // 1179648
#define NELEM (BB * COUT * HWSZ)     // 18874368
#define NQUAD (NPIX / 4)             // 294912 (HWSZ % 4 == 0 -> quads never cross batch)
#define MAX_ITERS 12
#define TPB   128
#define GRIDP 296                    // 2 blocks/SM on 148 SMs; capacity guaranteed >=3/SM

// ---------------- persistent device state ----------------
__device__ float            g_sums[MAX_ITERS + 2];
__device__ unsigned         g_count;     // barrier arrival counter (always returns to 0)
__device__ volatile unsigned g_epoch;    // barrier epoch (monotonic across graph replays)

// ---------------- packed f32x2 helpers (sm_103a FFMA2 path) ----------------
__device__ __forceinline__ unsigned long long pack2(float lo, float hi) {
    unsigned long long r;
    asm("mov.b64 %0, {%1,%2};" : "=l"(r) : "r"(__float_as_uint(lo)), "r"(__float_as_uint(hi)));
    return r;
}
__device__ __forceinline__ void unpack2(unsigned long long v, float& lo, float& hi) {
    unsigned int a, b;
    asm("mov.b64 {%0,%1}, %2;" : "=r"(a), "=r"(b) : "l"(v));
    lo = __uint_as_float(a); hi = __uint_as_float(b);
}
__device__ __forceinline__ unsigned long long ffma2(unsigned long long a, unsigned long long b,
                                                    unsigned long long c) {
    unsigned long long d;
    asm("fma.rn.f32x2 %0, %1, %2, %3;" : "=l"(d) : "l"(a), "l"(b), "l"(c));
    return d;
}
__device__ __forceinline__ unsigned long long fmul2(unsigned long long a, unsigned long long b) {
    unsigned long long d;
    asm("mul.rn.f32x2 %0, %1, %2;" : "=l"(d) : "l"(a), "l"(b));
    return d;
}
__device__ __forceinline__ unsigned long long fadd2(unsigned long long a, unsigned long long b) {
    unsigned long long d;
    asm("add.rn.f32x2 %0, %1, %2;" : "=l"(d) : "l"(a), "l"(b));
    return d;
}
#define ABS2(v)  ((v) & 0x7FFFFFFF7FFFFFFFULL)
#define TEN2     0x4120000041200000ULL   // {10.0f, 10.0f}

// fast tanh: 1 - 2/(e^{2x}+1); MUFU.EX2 + MUFU.RCP, rel err ~1e-6 (tol is 1e-3)
__device__ __forceinline__ float ftanh(float x) {
    float e = __expf(2.0f * x);                 // +inf -> result 1, 0 -> result -1: correct limits
    return 1.0f - __fdividef(2.0f, e + 1.0f);
}
__device__ __forceinline__ unsigned long long tanh2(unsigned long long a) {
    float lo, hi; unpack2(a, lo, hi);
    return pack2(ftanh(lo), ftanh(hi));
}

// ---------------- L2-coherent 16B vector ld/st (bypass L1 between barrier phases) ----------------
__device__ __forceinline__ ulonglong2 ldcg2(const float* p) {
    ulonglong2 r;
    asm volatile("ld.global.cg.v2.u64 {%0,%1}, [%2];" : "=l"(r.x), "=l"(r.y) : "l"(p));
    return r;
}
__device__ __forceinline__ void stcg2(float* p, ulonglong2 v) {
    asm volatile("st.global.cg.v2.u64 [%0], {%1,%2};" :: "l"(p), "l"(v.x), "l"(v.y) : "memory");
}
__device__ __forceinline__ float4 ldcg4f(const float* p) {
    float4 r;
    asm volatile("ld.global.cg.v4.f32 {%0,%1,%2,%3}, [%4];"
                 : "=f"(r.x), "=f"(r.y), "=f"(r.z), "=f"(r.w) : "l"(p));
    return r;
}

// ---------------- block + grid reduction / barrier ----------------
__device__ __forceinline__ void block_reduce_add(float val, float* target, float* warpsum) {
    #pragma unroll
    for (int off = 16; off; off >>= 1) val += __shfl_down_sync(0xffffffffu, val, off);
    int lane = threadIdx.x & 31, wid = threadIdx.x >> 5;
    if (lane == 0) warpsum[wid] = val;
    __syncthreads();
    if (wid == 0) {
        val = (lane < TPB / 32) ? warpsum[lane] : 0.0f;
        #pragma unroll
        for (int off = 16; off; off >>= 1) val += __shfl_down_sync(0xffffffffu, val, off);
        if (lane == 0) atomicAdd(target, val);
    }
    __syncthreads();   // warpsum reusable afterwards
}

__device__ __forceinline__ void grid_barrier(unsigned target) {
    __syncthreads();
    if (threadIdx.x == 0) {
        __threadfence();
        unsigned arrived = atomicAdd(&g_count, 1);
        if (arrived == GRIDP - 1) {
            g_count = 0;            // all others are spinning; safe to reset
            __threadfence();
            g_epoch = target;       // release
        } else {
            while (g_epoch != target) { __nanosleep(64); }
        }
        __threadfence();            // acquire
    }
    __syncthreads();
}

// ---------------- the persistent kernel ----------------
__global__ void __launch_bounds__(TPB, 3)
persist_kernel(const float* __restrict__ x,
               const float* __restrict__ w_pre,  const float* __restrict__ b_pre,
               const float* __restrict__ w_loop, const float* __restrict__ b_loop,
               const float* __restrict__ w_sh,   const float* __restrict__ b_sh,
               float* __restrict__ v /* = d_out, in-place state buffer */) {
    __shared__ float swpre[COUT * CIN];
    __shared__ float sbpre[COUT];
    __shared__ __align__(16) float ws2[COUT][2 * COUT];   // {w,w} duplicated pairs
    __shared__ __align__(16) float wl2[COUT][2 * COUT];
    __shared__ unsigned long long bs2[COUT], bl2[COUT];
    __shared__ float warpsum[TPB / 32];
    __shared__ unsigned s_ep0;

    const int tid = threadIdx.x;

    // stage weights into smem (duplicated pairs for f32x2 operands)
    for (int i = tid; i < COUT * COUT; i += TPB) {
        int o = i >> 4, c = i & 15;
        float a = w_sh[i];   ws2[o][2 * c] = a; ws2[o][2 * c + 1] = a;
        float b = w_loop[i]; wl2[o][2 * c] = b; wl2[o][2 * c + 1] = b;
    }
    if (tid < COUT * CIN) swpre[tid] = w_pre[tid];
    if (tid < COUT) {
        sbpre[tid] = b_pre[tid];
        bs2[tid] = pack2(b_sh[tid],   b_sh[tid]);
        bl2[tid] = pack2(b_loop[tid], b_loop[tid]);
    }
    if (tid == 0) s_ep0 = g_epoch;   // stable: no barrier can complete before this block arrives
    // reset per-replay accumulators (block 0), published by barrier fence below
    if (blockIdx.x == 0 && tid < MAX_ITERS + 2) g_sums[tid] = 0.0f;
    __syncthreads();

    const unsigned epb = s_ep0;
    unsigned bk = 0;
    grid_barrier(epb + (++bk));      // sums zeroed & visible before any accumulation

    const int gtid   = blockIdx.x * TPB + tid;
    const int stride = GRIDP * TPB;

    // ---------- PRE: v = w_pre @ x + b_pre ; sum |v| -> g_sums[0] ----------
    {
        float local = 0.0f;
        for (int q = gtid; q < NQUAD; q += stride) {
            int p = q * 4;
            int b = p / HWSZ;
            int hw = p - b * HWSZ;
            const float* xb = x + b * CIN * HWSZ + hw;
            float4 x0 = ldcg4f(xb);
            float4 x1 = ldcg4f(xb + HWSZ);
            float4 x2 = ldcg4f(xb + 2 * HWSZ);
            float* vb = v + b * COUT * HWSZ + hw;
            #pragma unroll
            for (int o = 0; o < COUT; o++) {
                float w0 = swpre[o * 3], w1 = swpre[o * 3 + 1], w2 = swpre[o * 3 + 2];
                float bb = sbpre[o];
                float r0 = fmaf(w0, x0.x, fmaf(w1, x1.x, fmaf(w2, x2.x, bb)));
                float r1 = fmaf(w0, x0.y, fmaf(w1, x1.y, fmaf(w2, x2.y, bb)));
                float r2 = fmaf(w0, x0.z, fmaf(w1, x1.z, fmaf(w2, x2.z, bb)));
                float r3 = fmaf(w0, x0.w, fmaf(w1, x1.w, fmaf(w2, x2.w, bb)));
                ulonglong2 u; u.x = pack2(r0, r1); u.y = pack2(r2, r3);
                stcg2(vb + o * HWSZ, u);
                local += fabsf(r0) + fabsf(r1) + fabsf(r2) + fabsf(r3);
            }
        }
        block_reduce_add(local, &g_sums[0], warpsum);
        __threadfence();
        grid_barrier(epb + (++bk));
    }

    // ---------- WHILE loop: v = 10*(w_loop @ tanh(w_sh @ v + b_sh) + b_loop) ----------
    unsigned it = 0;
    while (true) {
        float s = ((volatile float*)g_sums)[it];
        if (!(s * (1.0f / (float)NELEM) < 3.0f) || it >= MAX_ITERS) break;

        unsigned long long s2 = 0ULL;   // packed {0,0} abs-accumulator
        for (int q = gtid; q < NQUAD; q += stride) {
            int p = q * 4;
            int b = p / HWSZ;
            int hw = p - b * HWSZ;
            float* vb = v + b * COUT * HWSZ + hw;

            ulonglong2 vin[COUT];       // .x = pixels(0,1), .y = pixels(2,3)
            #pragma unroll
            for (int c = 0; c < COUT; c++) vin[c] = ldcg2(vb + c * HWSZ);

            unsigned long long t01[COUT], t23[COUT];
            #pragma unroll
            for (int o = 0; o < COUT; o++) {
                unsigned long long a01 = bs2[o], a23 = bs2[o];
                const ulonglong2* wrow = (const ulonglong2*)ws2[o];
                #pragma unroll
                for (int k = 0; k < 8; k++) {
                    ulonglong2 w = wrow[k];          // {w2k,w2k} , {w2k+1,w2k+1}
                    a01 = ffma2(w.x, vin[2 * k].x,     a01);
                    a23 = ffma2(w.x, vin[2 * k].y,     a23);
                    a01 = ffma2(w.y, vin[2 * k + 1].x, a01);
                    a23 = ffma2(w.y, vin[2 * k + 1].y, a23);
                }
                t01[o] = tanh2(a01);
                t23[o] = tanh2(a23);
            }

            #pragma unroll
            for (int o = 0; o < COUT; o++) {
                unsigned long long a01 = bl2[o], a23 = bl2[o];
                const ulonglong2* wrow = (const ulonglong2*)wl2[o];
                #pragma unroll
                for (int k = 0; k < 8; k++) {
                    ulonglong2 w = wrow[k];
                    a01 = ffma2(w.x, t01[2 * k],     a01);
                    a23 = ffma2(w.x, t23[2 * k],     a23);
                    a01 = ffma2(w.y, t01[2 * k + 1], a01);
                    a23 = ffma2(w.y, t23[2 * k + 1], a23);
                }
                a01 = fmul2(a01, TEN2);
                a23 = fmul2(a23, TEN2);
                ulonglong2 u; u.x = a01; u.y = a23;
                stcg2(vb + o * HWSZ, u);
                s2 = fadd2(s2, ABS2(a01));
                s2 = fadd2(s2, ABS2(a23));
            }
        }
        float lo, hi; unpack2(s2, lo, hi);
        block_reduce_add(lo + hi, &g_sums[it + 1], warpsum);
        __threadfence();
        grid_barrier(epb + (++bk));
        it++;
    }

    // ---------- FINAL: out = w_sh @ v + b_sh (in place) ----------
    for (int q = gtid; q < NQUAD; q += stride) {
        int p = q * 4;
        int b = p / HWSZ;
        int hw = p - b * HWSZ;
        float* vb = v + b * COUT * HWSZ + hw;

        ulonglong2 vin[COUT];
        #pragma unroll
        for (int c = 0; c < COUT; c++) vin[c] = ldcg2(vb + c * HWSZ);

        #pragma unroll
        for (int o = 0; o < COUT; o++) {
            unsigned long long a01 = bs2[o], a23 = bs2[o];
            const ulonglong2* wrow = (const ulonglong2*)ws2[o];
            #pragma unroll
            for (int k = 0; k < 8; k++) {
                ulonglong2 w = wrow[k];
                a01 = ffma2(w.x, vin[2 * k].x,     a01);
                a23 = ffma2(w.x, vin[2 * k].y,     a23);
                a01 = ffma2(w.y, vin[2 * k + 1].x, a01);
                a23 = ffma2(w.y, vin[2 * k + 1].y, a23);
            }
            ulonglong2 u; u.x = a01; u.y = a23;
            stcg2(vb + o * HWSZ, u);
        }
    }
}

extern "C" void kernel_launch(void* const* d_in, const int* in_sizes, int n_in,
                              void* d_out, int out_size) {
    const float* x        = (const float*)d_in[0];
    const float* w_pre    = (const float*)d_in[1];
    const float* b_pre    = (const float*)d_in[2];
    const float* w_loop   = (const float*)d_in[3];
    const float* b_loop   = (const float*)d_in[4];
    const float* w_shared = (const float*)d_in[5];
    const float* b_shared = (const float*)d_in[6];
    float* out = (float*)d_out;

    persist_kernel<<<GRIDP, TPB>>>(x, w_pre, b_pre, w_loop, b_loop,
                                   w_shared, b_shared, out);
}

// round 3
// speedup vs baseline: 1.7867x; 1.1295x over previous
#include <cuda_runtime.h>
#include <math.h>

// ---------------- problem constants ----------------
#define BB    8
#define CIN   3
#define COUT  16
#define HWSZ  147456                 // 384*384
#define NPIX  (BB * HWSZ)            // 1179648
#define NELEM (BB * COUT * HWSZ)     // 18874368
#define NQUAD (NPIX / 4)             // 294912 (HWSZ % 4 == 0 -> quads never cross batch)
#define MAX_ITERS 12
#define TPB   256
#define GRIDP 296                    // 2 blocks/SM on 148 SMs

// ---------------- persistent device state ----------------
__device__ float             g_sums[MAX_ITERS + 2];
__device__ unsigned          g_count;
__device__ volatile unsigned g_epoch;

// ---------------- packed f32x2 helpers ----------------
__device__ __forceinline__ unsigned long long pack2(float lo, float hi) {
    unsigned long long r;
    asm("mov.b64 %0, {%1,%2};" : "=l"(r) : "r"(__float_as_uint(lo)), "r"(__float_as_uint(hi)));
    return r;
}
__device__ __forceinline__ void unpack2(unsigned long long v, float& lo, float& hi) {
    unsigned int a, b;
    asm("mov.b64 {%0,%1}, %2;" : "=r"(a), "=r"(b) : "l"(v));
    lo = __uint_as_float(a); hi = __uint_as_float(b);
}
__device__ __forceinline__ unsigned long long ffma2(unsigned long long a, unsigned long long b,
                                                    unsigned long long c) {
    unsigned long long d;
    asm("fma.rn.f32x2 %0, %1, %2, %3;" : "=l"(d) : "l"(a), "l"(b), "l"(c));
    return d;
}
__device__ __forceinline__ unsigned long long fmul2(unsigned long long a, unsigned long long b) {
    unsigned long long d;
    asm("mul.rn.f32x2 %0, %1, %2;" : "=l"(d) : "l"(a), "l"(b));
    return d;
}
__device__ __forceinline__ unsigned long long fadd2(unsigned long long a, unsigned long long b) {
    unsigned long long d;
    asm("add.rn.f32x2 %0, %1, %2;" : "=l"(d) : "l"(a), "l"(b));
    return d;
}
#define ABS2(v)  ((v) & 0x7FFFFFFF7FFFFFFFULL)
#define TEN2     0x4120000041200000ULL   // {10.0f, 10.0f}

// single-instruction MUFU.TANH (sm_75+); abs err ~1.5e-4 << 1e-3 tolerance
__device__ __forceinline__ float ftanh(float x) {
    float y;
    asm("tanh.approx.f32 %0, %1;" : "=f"(y) : "f"(x));
    return y;
}
__device__ __forceinline__ unsigned long long tanh2(unsigned long long a) {
    float lo, hi; unpack2(a, lo, hi);
    return pack2(ftanh(lo), ftanh(hi));
}

// ---------------- L2-coherent vector ld/st (L1 bypass across barrier phases) ----------------
__device__ __forceinline__ ulonglong2 ldcg2(const float* p) {
    ulonglong2 r;
    asm volatile("ld.global.cg.v2.u64 {%0,%1}, [%2];" : "=l"(r.x), "=l"(r.y) : "l"(p));
    return r;
}
__device__ __forceinline__ void stcg2(float* p, unsigned long long a, unsigned long long b) {
    asm volatile("st.global.cg.v2.u64 [%0], {%1,%2};" :: "l"(p), "l"(a), "l"(b) : "memory");
}
__device__ __forceinline__ float4 ldcg4f(const float* p) {
    float4 r;
    asm volatile("ld.global.cg.v4.f32 {%0,%1,%2,%3}, [%4];"
                 : "=f"(r.x), "=f"(r.y), "=f"(r.z), "=f"(r.w) : "l"(p));
    return r;
}

// ---------------- block reduction + grid barrier ----------------
__device__ __forceinline__ void block_reduce_add(float val, float* target, float* warpsum) {
    #pragma unroll
    for (int off = 16; off; off >>= 1) val += __shfl_down_sync(0xffffffffu, val, off);
    int lane = threadIdx.x & 31, wid = threadIdx.x >> 5;
    if (lane == 0) warpsum[wid] = val;
    __syncthreads();
    if (wid == 0) {
        val = (lane < TPB / 32) ? warpsum[lane] : 0.0f;
        #pragma unroll
        for (int off = 16; off; off >>= 1) val += __shfl_down_sync(0xffffffffu, val, off);
        if (lane == 0) atomicAdd(target, val);
    }
    __syncthreads();
}

__device__ __forceinline__ void grid_barrier(unsigned target) {
    __syncthreads();
    if (threadIdx.x == 0) {
        __threadfence();
        unsigned arrived = atomicAdd(&g_count, 1);
        if (arrived == GRIDP - 1) {
            g_count = 0;
            __threadfence();
            g_epoch = target;      // release
        } else {
            while (g_epoch != target) { __nanosleep(64); }
        }
        __threadfence();           // acquire
    }
    __syncthreads();
}

// ---------------- the persistent kernel ----------------
__global__ void __launch_bounds__(TPB, 2)
persist_kernel(const float* __restrict__ x,
               const float* __restrict__ w_pre,  const float* __restrict__ b_pre,
               const float* __restrict__ w_loop, const float* __restrict__ b_loop,
               const float* __restrict__ w_sh,   const float* __restrict__ b_sh,
               float* __restrict__ v /* = d_out, in-place state buffer */) {
    __shared__ float swpre[COUT * CIN];
    __shared__ float sbpre[COUT];
    // wsT2[c][o]: w_sh transposed, duplicated {w,w} pairs (for channel-streaming GEMM1)
    // wl2 [o][c]: w_loop row-major, duplicated pairs (for output-streaming GEMM2)
    __shared__ __align__(16) unsigned long long wsT2[COUT][COUT];
    __shared__ __align__(16) unsigned long long wl2[COUT][COUT];
    __shared__ unsigned long long bs2[COUT], bl2[COUT];
    __shared__ float warpsum[TPB / 32];
    __shared__ unsigned s_ep0;

    const int tid = threadIdx.x;

    for (int i = tid; i < COUT * COUT; i += TPB) {
        int o = i >> 4, c = i & 15;
        float a = w_sh[i];   wsT2[c][o] = pack2(a, a);
        float b = w_loop[i]; wl2[o][c]  = pack2(b, b);
    }
    if (tid < COUT * CIN) swpre[tid] = w_pre[tid];
    if (tid < COUT) {
        sbpre[tid] = b_pre[tid];
        bs2[tid] = pack2(b_sh[tid],   b_sh[tid]);
        bl2[tid] = pack2(b_loop[tid], b_loop[tid]);
    }
    if (tid == 0) s_ep0 = g_epoch;
    if (blockIdx.x == 0 && tid < MAX_ITERS + 2) g_sums[tid] = 0.0f;
    __syncthreads();

    const unsigned epb = s_ep0;
    unsigned bk = 0;
    grid_barrier(epb + (++bk));      // sums zeroed & visible

    const int gtid   = blockIdx.x * TPB + tid;
    const int stride = GRIDP * TPB;

    // ---------- PRE: v = w_pre @ x + b_pre ; sum |v| -> g_sums[0] ----------
    {
        float local = 0.0f;
        for (int q = gtid; q < NQUAD; q += stride) {
            int p = q * 4;
            int b = p / HWSZ;
            int hw = p - b * HWSZ;
            const float* xb = x + b * CIN * HWSZ + hw;
            float4 x0 = ldcg4f(xb);
            float4 x1 = ldcg4f(xb + HWSZ);
            float4 x2 = ldcg4f(xb + 2 * HWSZ);
            float* vb = v + b * COUT * HWSZ + hw;
            #pragma unroll
            for (int o = 0; o < COUT; o++) {
                float w0 = swpre[o * 3], w1 = swpre[o * 3 + 1], w2 = swpre[o * 3 + 2];
                float bb = sbpre[o];
                float r0 = fmaf(w0, x0.x, fmaf(w1, x1.x, fmaf(w2, x2.x, bb)));
                float r1 = fmaf(w0, x0.y, fmaf(w1, x1.y, fmaf(w2, x2.y, bb)));
                float r2 = fmaf(w0, x0.z, fmaf(w1, x1.z, fmaf(w2, x2.z, bb)));
                float r3 = fmaf(w0, x0.w, fmaf(w1, x1.w, fmaf(w2, x2.w, bb)));
                stcg2(vb + o * HWSZ, pack2(r0, r1), pack2(r2, r3));
                local += fabsf(r0) + fabsf(r1) + fabsf(r2) + fabsf(r3);
            }
        }
        block_reduce_add(local, &g_sums[0], warpsum);
        __threadfence();
        grid_barrier(epb + (++bk));
    }

    // ---------- WHILE: v = 10*(w_loop @ tanh(w_sh @ v + b_sh) + b_loop) ----------
    unsigned it = 0;
    while (true) {
        float s = ((volatile float*)g_sums)[it];
        if (!(s * (1.0f / (float)NELEM) < 3.0f) || it >= MAX_ITERS) break;

        unsigned long long s2 = 0ULL;
        for (int q = gtid; q < NQUAD; q += stride) {
            int p = q * 4;
            int b = p / HWSZ;
            int hw = p - b * HWSZ;
            float* vb = v + b * COUT * HWSZ + hw;

            // GEMM1 (channel-streaming): acc[o] = b_sh[o] + sum_c w_sh[o][c]*v[c]
            ulonglong2 acc[COUT];            // .x = pixels(0,1), .y = pixels(2,3)
            #pragma unroll
            for (int o = 0; o < COUT; o++) { acc[o].x = bs2[o]; acc[o].y = bs2[o]; }
            #pragma unroll
            for (int c = 0; c < COUT; c++) {
                ulonglong2 vc = ldcg2(vb + c * HWSZ);
                const ulonglong2* wc = (const ulonglong2*)wsT2[c];
                #pragma unroll
                for (int k = 0; k < 8; k++) {
                    ulonglong2 w = wc[k];    // weights for outputs 2k, 2k+1
                    acc[2 * k].x     = ffma2(w.x, vc.x, acc[2 * k].x);
                    acc[2 * k].y     = ffma2(w.x, vc.y, acc[2 * k].y);
                    acc[2 * k + 1].x = ffma2(w.y, vc.x, acc[2 * k + 1].x);
                    acc[2 * k + 1].y = ffma2(w.y, vc.y, acc[2 * k + 1].y);
                }
            }
            // tanh in place: acc becomes t
            #pragma unroll
            for (int o = 0; o < COUT; o++) {
                acc[o].x = tanh2(acc[o].x);
                acc[o].y = tanh2(acc[o].y);
            }
            // GEMM2 (output-streaming): emit one output channel at a time
            #pragma unroll
            for (int o = 0; o < COUT; o++) {
                unsigned long long a01 = bl2[o], a23 = bl2[o];
                const ulonglong2* wrow = (const ulonglong2*)wl2[o];
                #pragma unroll
                for (int k = 0; k < 8; k++) {
                    ulonglong2 w = wrow[k];
                    a01 = ffma2(w.x, acc[2 * k].x,     a01);
                    a23 = ffma2(w.x, acc[2 * k].y,     a23);
                    a01 = ffma2(w.y, acc[2 * k + 1].x, a01);
                    a23 = ffma2(w.y, acc[2 * k + 1].y, a23);
                }
                a01 = fmul2(a01, TEN2);
                a23 = fmul2(a23, TEN2);
                stcg2(vb + o * HWSZ, a01, a23);
                s2 = fadd2(s2, ABS2(a01));
                s2 = fadd2(s2, ABS2(a23));
            }
        }
        float lo, hi; unpack2(s2, lo, hi);
        block_reduce_add(lo + hi, &g_sums[it + 1], warpsum);
        __threadfence();
        grid_barrier(epb + (++bk));
        it++;
    }

    // ---------- FINAL: out = w_sh @ v + b_sh (in place) ----------
    for (int q = gtid; q < NQUAD; q += stride) {
        int p = q * 4;
        int b = p / HWSZ;
        int hw = p - b * HWSZ;
        float* vb = v + b * COUT * HWSZ + hw;

        ulonglong2 acc[COUT];
        #pragma unroll
        for (int o = 0; o < COUT; o++) { acc[o].x = bs2[o]; acc[o].y = bs2[o]; }
        #pragma unroll
        for (int c = 0; c < COUT; c++) {
            ulonglong2 vc = ldcg2(vb + c * HWSZ);
            const ulonglong2* wc = (const ulonglong2*)wsT2[c];
            #pragma unroll
            for (int k = 0; k < 8; k++) {
                ulonglong2 w = wc[k];
                acc[2 * k].x     = ffma2(w.x, vc.x, acc[2 * k].x);
                acc[2 * k].y     = ffma2(w.x, vc.y, acc[2 * k].y);
                acc[2 * k + 1].x = ffma2(w.y, vc.x, acc[2 * k + 1].x);
                acc[2 * k + 1].y = ffma2(w.y, vc.y, acc[2 * k + 1].y);
            }
        }
        #pragma unroll
        for (int o = 0; o < COUT; o++)
            stcg2(vb + o * HWSZ, acc[o].x, acc[o].y);
    }
}

extern "C" void kernel_launch(void* const* d_in, const int* in_sizes, int n_in,
                              void* d_out, int out_size) {
    const float* x        = (const float*)d_in[0];
    const float* w_pre    = (const float*)d_in[1];
    const float* b_pre    = (const float*)d_in[2];
    const float* w_loop   = (const float*)d_in[3];
    const float* b_loop   = (const float*)d_in[4];
    const float* w_shared = (const float*)d_in[5];
    const float* b_shared = (const float*)d_in[6];
    float* out = (float*)d_out;

    persist_kernel<<<GRIDP, TPB>>>(x, w_pre, b_pre, w_loop, b_loop,
                                   w_shared, b_shared, out);
}